// round 8
// baseline (speedup 1.0000x reference)
#include <cuda_runtime.h>
#include <cstdint>

// Problem constants (fixed by the dataset)
#define NTAB     8
#define BUCKETS  524288          // 2^19
#define BMASK    (BUCKETS - 1)
#define T_LEN    4096
#define HIST     128             // deepest lag
#define POS      64              // positions per group (kernel A)
#define THREADS  256
#define EXT      (POS + 120)     // 184: h8 needed at positions [t0-120, t0+POS)
#define MAXB     8               // max batch rows

// Hash primes (low-32-bit arithmetic is exact for the %2^19 result)
#define P0 2654435761u
#define P1 2246822519u
#define P2 3266489917u
#define P3 2028178513u
#define P4 1220703125u
#define P5 1610612741u
#define P6 805306457u
#define P7 402653189u

// Scratch: bucket id per (row, t, table). 8*4096*8 ints = 1 MB.
__device__ int g_idx[MAXB * T_LEN * NTAB];

// ============================ Kernel A: indices ============================
__global__ void __launch_bounds__(THREADS)
index_kernel(const void* __restrict__ tokens_raw)
{
    __shared__ int      tok_s[HIST + POS];
    __shared__ unsigned A[EXT], Bf[EXT];
    __shared__ int      idx_s[POS * NTAB];
    __shared__ int      is32_s;

    const int*       tok32 = (const int*)tokens_raw;
    const long long* tok64 = (const long long*)tokens_raw;
    const int tid = threadIdx.x;

    // Inline dtype probe: int64 tokens (<2^31) have all-zero odd words.
    if (tid < 32) {
        unsigned any = __ballot_sync(0xFFFFFFFFu, tok32[2 * tid + 1] != 0);
        if (tid == 0) is32_s = (any != 0u);
    }

    const int groups_per_row = T_LEN / POS;       // 64
    const int row = blockIdx.x / groups_per_row;
    const int t0  = (blockIdx.x % groups_per_row) * POS;

    __syncthreads();
    const int is32 = is32_s;

    // Stage tokens t0-128 .. t0+POS-1 (zero-padded)
    for (int i = tid; i < HIST + POS; i += THREADS) {
        const int t = t0 - HIST + i;
        int v = 0;
        if (t >= 0) {
            const size_t k = (size_t)row * T_LEN + t;
            v = is32 ? tok32[k] : (int)tok64[k];
        }
        tok_s[i] = v;
    }
    __syncthreads();

    // h1,h2,h4,h8 chains. Position p = t0-120+i; lag-k token is tok_s[i+7-k].
    if (tid < EXT) {
        const int i = tid;
        const bool snap = (i >= 120);
        const int  tp   = i - 120;
        unsigned h = (unsigned)tok_s[i + 7] * P0;                    // window 1
        if (snap) idx_s[tp * NTAB + 0] = (int)(h & BMASK);
        h ^= (unsigned)tok_s[i + 6] * P1;                            // window 2
        if (snap) idx_s[tp * NTAB + 1] = (int)(h & BMASK);
        h ^= (unsigned)tok_s[i + 5] * P2;
        h ^= (unsigned)tok_s[i + 4] * P3;                            // window 4
        if (snap) idx_s[tp * NTAB + 2] = (int)(h & BMASK);
        h ^= (unsigned)tok_s[i + 3] * P4;
        h ^= (unsigned)tok_s[i + 2] * P5;
        h ^= (unsigned)tok_s[i + 1] * P6;
        h ^= (unsigned)tok_s[i + 0] * P7;                            // window 8
        A[i] = h;
        if (snap) idx_s[tp * NTAB + 3] = (int)(h & BMASK);
    }
    __syncthreads();

    // Log-doubling: h_{2w}(p) = h_w(p) ^ h_w(p-w).
    if (tid < EXT && tid >= 8) {                 // window 16
        unsigned h = A[tid] ^ A[tid - 8];
        Bf[tid] = h;
        if (tid >= 120) idx_s[(tid - 120) * NTAB + 4] = (int)(h & BMASK);
    }
    __syncthreads();
    if (tid < EXT && tid >= 24) {                // window 32
        unsigned h = Bf[tid] ^ Bf[tid - 16];
        A[tid] = h;
        if (tid >= 120) idx_s[(tid - 120) * NTAB + 5] = (int)(h & BMASK);
    }
    __syncthreads();
    if (tid < EXT && tid >= 56) {                // window 64
        unsigned h = A[tid] ^ A[tid - 32];
        Bf[tid] = h;
        if (tid >= 120) idx_s[(tid - 120) * NTAB + 6] = (int)(h & BMASK);
    }
    __syncthreads();
    if (tid >= 120 && tid < EXT) {               // window 128
        unsigned h = Bf[tid] ^ Bf[tid - 64];
        idx_s[(tid - 120) * NTAB + 7] = (int)(h & BMASK);
    }
    __syncthreads();

    // Write indices (coalesced, layout matches gather row order)
    const int base = (row * T_LEN + t0) * NTAB;
    #pragma unroll
    for (int i = tid; i < POS * NTAB; i += THREADS)
        g_idx[base + i] = idx_s[i];
}

// ====================== Kernel B: pure streaming gather =====================
// 32B unit u: row rw = u>>3 (= (bt*T+t)*8 + tbl), chunk c8 = u&7.
// Each block covers 1024 consecutive units (32 KiB of output).
__global__ void __launch_bounds__(THREADS, 5)
gather_kernel(const char* __restrict__ tables, char* __restrict__ out)
{
    const int tid = threadIdx.x;
    const unsigned u0 = blockIdx.x * 1024u;

    const char* src[4];
    #pragma unroll
    for (int it = 0; it < 4; ++it) {
        const unsigned u  = u0 + it * THREADS + tid;
        const int rw  = (int)(u >> 3);
        const int c8  = (int)(u & 7);
        const int tbl = rw & 7;
        const int bucket = __ldg(&g_idx[rw]);    // broadcast within 8 lanes
        src[it] = tables + ((((size_t)tbl * BUCKETS + (size_t)bucket) << 8)
                            | ((size_t)c8 << 5));
    }

    unsigned long long d0[4], d1[4], d2[4], d3[4];
    #pragma unroll
    for (int it = 0; it < 4; ++it) {
        asm volatile("ld.global.nc.L2::evict_last.v4.b64 {%0,%1,%2,%3}, [%4];"
                     : "=l"(d0[it]), "=l"(d1[it]), "=l"(d2[it]), "=l"(d3[it])
                     : "l"(src[it]));
    }
    #pragma unroll
    for (int it = 0; it < 4; ++it) {
        char* dst = out + (((size_t)u0 + (size_t)(it * THREADS + tid)) << 5);
        asm volatile("st.global.L2::evict_first.v4.b64 [%0], {%1,%2,%3,%4};"
                     :: "l"(dst), "l"(d0[it]), "l"(d1[it]), "l"(d2[it]), "l"(d3[it])
                     : "memory");
    }
}

extern "C" void kernel_launch(void* const* d_in, const int* in_sizes, int n_in,
                              void* d_out, int out_size)
{
    const void* tokens = d_in[0];                 // int64 OR int32 (B, T) — probed
    const char* tables = (const char*)d_in[1];    // fp32 (8, 524288, 64)
    char*       out    = (char*)d_out;            // fp32 (B, T, 512)

    const int rows = in_sizes[0] / T_LEN;         // B = 8
    const int gridA = rows * (T_LEN / POS);       // 512
    // total 32B units = rows * T * 512 floats * 4B / 32B = rows * T * 64
    const int gridB = rows * T_LEN * 64 / 1024;   // 2048

    index_kernel <<<gridA, THREADS>>>(tokens);
    gather_kernel<<<gridB, THREADS>>>(tables, out);
}